// round 2
// baseline (speedup 1.0000x reference)
#include <cuda_runtime.h>

// Problem constants
#define BATCH 8
#define NUM   128
#define CH    512          // = H * D_K
#define HEADS 8
#define DK    64
#define NPOS  (BATCH*NUM*NUM)   // 131072 positions (b, i, j)
#define EPSV  1e-8f

// Global column mask (set of columns appearing in any top-4). No alloc allowed,
// so it lives in device global memory.
__device__ float g_colmask[NUM];

// ---------------------------------------------------------------------------
// Kernel 1: cosine-similarity attention.
// 256 threads per block, 2 positions per block (128 threads per position).
// Thread t of a position loads float4 q[4t..4t+3], k[4t..4t+3]; head = t/16.
// Reduce dot/qq/kk across the 16-lane head group via xor shuffles.
// Writes attn[pos*8 + h] = relu(dot / max(sqrt(qq*kk), eps)) into d_out.
// Block 0 additionally zeroes g_colmask (stream-ordered before kernel 2).
// ---------------------------------------------------------------------------
__global__ __launch_bounds__(256) void attn_kernel(
    const float* __restrict__ q,
    const float* __restrict__ k,
    float* __restrict__ out)
{
    const int local = threadIdx.x;          // 0..255
    const int t     = local & 127;          // thread within position
    const int pos   = blockIdx.x * 2 + (local >> 7);

    if (blockIdx.x == 0 && local < NUM) g_colmask[local] = 0.0f;

    const float4* q4 = reinterpret_cast<const float4*>(q + (size_t)pos * CH);
    const float4* k4 = reinterpret_cast<const float4*>(k + (size_t)pos * CH);

    float4 a = q4[t];
    float4 b = k4[t];

    float dot = a.x*b.x + a.y*b.y + a.z*b.z + a.w*b.w;
    float qq  = a.x*a.x + a.y*a.y + a.z*a.z + a.w*a.w;
    float kk  = b.x*b.x + b.y*b.y + b.z*b.z + b.w*b.w;

    // Reduce across the 16-lane group belonging to one head.
    #pragma unroll
    for (int m = 8; m; m >>= 1) {
        dot += __shfl_xor_sync(0xffffffffu, dot, m);
        qq  += __shfl_xor_sync(0xffffffffu, qq,  m);
        kk  += __shfl_xor_sync(0xffffffffu, kk,  m);
    }

    if ((t & 15) == 0) {
        int h = t >> 4;
        float denom = fmaxf(sqrtf(qq * kk), EPSV);
        float s = dot / denom;
        out[(size_t)pos * HEADS + h] = fmaxf(s, 0.0f);
    }
}

// ---------------------------------------------------------------------------
// Kernel 2: per-(b,i,h) top-4 over j (128 candidates), OR the winning column
// indices into g_colmask. One block per (b,i): 256 threads, 8 warps = 8 heads.
// Tile staged to smem transposed [h][j] with row pad 132 (conflict-free).
// Warp argmax with lowest-index tiebreak (matches lax.top_k ordering).
// ---------------------------------------------------------------------------
__global__ __launch_bounds__(256) void topk_kernel(const float* __restrict__ attn)
{
    __shared__ float sm[HEADS * 132];

    const int bi   = blockIdx.x;                  // (b*NUM + i), 0..1023
    const int tidx = threadIdx.x;                 // 0..255
    const float* row = attn + (size_t)bi * NUM * HEADS;  // 128 j x 8 h

    // Load 1024 floats, transpose into sm[h*132 + j]
    #pragma unroll
    for (int r = 0; r < 4; ++r) {
        int idx = tidx + r * 256;                 // idx = j*8 + h
        int h = idx & 7;
        int j = idx >> 3;
        sm[h * 132 + j] = row[idx];
    }
    __syncthreads();

    const int warp = tidx >> 5;                   // head
    const int lane = tidx & 31;

    float vals[4];
    #pragma unroll
    for (int m = 0; m < 4; ++m)
        vals[m] = sm[warp * 132 + lane + 32 * m];

    bool used[4] = {false, false, false, false};

    #pragma unroll
    for (int it = 0; it < 4; ++it) {
        float bv = -3.402823466e+38f;
        int   bi_idx = 1 << 30;
        #pragma unroll
        for (int m = 0; m < 4; ++m) {
            int j = lane + 32 * m;
            if (!used[m] && (vals[m] > bv || (vals[m] == bv && j < bi_idx))) {
                bv = vals[m];
                bi_idx = j;
            }
        }
        // Warp argmax, min-index tiebreak — butterfly converges identically on
        // all lanes.
        #pragma unroll
        for (int m = 16; m; m >>= 1) {
            float ov = __shfl_xor_sync(0xffffffffu, bv, m);
            int   oi = __shfl_xor_sync(0xffffffffu, bi_idx, m);
            if (ov > bv || (ov == bv && oi < bi_idx)) { bv = ov; bi_idx = oi; }
        }
        // Mark winner consumed on its owner lane.
        #pragma unroll
        for (int m = 0; m < 4; ++m)
            if (lane + 32 * m == bi_idx) used[m] = true;

        if (lane == 0) g_colmask[bi_idx] = 1.0f;   // benign race: same value
    }
}

// ---------------------------------------------------------------------------
// Kernel 3: out[b,i,j,:] *= roi[b,i,j] * colmask[j]. One thread per position,
// two float4 read-modify-writes (32B contiguous per thread).
// ---------------------------------------------------------------------------
__global__ __launch_bounds__(256) void apply_kernel(
    float* __restrict__ out,
    const float* __restrict__ roi)
{
    const int p = blockIdx.x * blockDim.x + threadIdx.x;   // 0..NPOS-1
    const int j = p & (NUM - 1);
    const float scale = roi[p] * g_colmask[j];

    float4* o = reinterpret_cast<float4*>(out + (size_t)p * HEADS);
    float4 x0 = o[0];
    float4 x1 = o[1];
    x0.x *= scale; x0.y *= scale; x0.z *= scale; x0.w *= scale;
    x1.x *= scale; x1.y *= scale; x1.z *= scale; x1.w *= scale;
    o[0] = x0;
    o[1] = x1;
}

// ---------------------------------------------------------------------------
extern "C" void kernel_launch(void* const* d_in, const int* in_sizes, int n_in,
                              void* d_out, int out_size)
{
    const float* q   = (const float*)d_in[0];
    const float* k   = (const float*)d_in[1];
    const float* roi = (const float*)d_in[2];
    float* out = (float*)d_out;

    // Kernel 1: attention + colmask zeroing. 2 positions per 256-thread block.
    attn_kernel<<<NPOS / 2, 256>>>(q, k, out);

    // Kernel 2: top-4 per (b,i,h) -> colmask. One block per (b,i).
    topk_kernel<<<BATCH * NUM, 256>>>(out);

    // Kernel 3: apply roi * colmask. One thread per (b,i,j).
    apply_kernel<<<NPOS / 256, 256>>>(out, roi);
}